// round 2
// baseline (speedup 1.0000x reference)
#include <cuda_runtime.h>

// ---------------------------------------------------------------------------
// SelfAttention: B=8, S=2048, D=768, DIM_K=DIM_V=768
//   Q = x@Wq + bq ; K = x@Wk + bk ; V = x@Wv + bv
//   scores = Q K^T  (per batch)
//   scores *= mask[b,s]  (query-row multiplicative mask)
//   attn = softmax(scores, axis=-1) * (1/sqrt(768))
//   out = attn @ V
// Round 1: full-fp32 tiled SGEMMs using packed fma.rn.f32x2 (FFMA2).
// ---------------------------------------------------------------------------

#define B_   8
#define S_   2048
#define D_   768
#define M_TOT (B_ * S_)          // 16384
#define NORM_CONST 0.036084391824351615f  // 1/sqrt(768)

// Scratch (static __device__ -> no runtime allocation)
__device__ float g_Q[M_TOT * D_];
__device__ float g_K[M_TOT * D_];
__device__ float g_V[M_TOT * D_];
__device__ float g_S[B_ * S_ * S_];

// ---------------------------------------------------------------------------
// f32x2 helpers
// ---------------------------------------------------------------------------
__device__ __forceinline__ unsigned long long pack2_dup(float x) {
    unsigned long long r;
    unsigned u = __float_as_uint(x);
    asm("mov.b64 %0, {%1, %2};" : "=l"(r) : "r"(u), "r"(u));
    return r;
}
__device__ __forceinline__ unsigned long long fma2(unsigned long long a,
                                                   unsigned long long b,
                                                   unsigned long long c) {
    unsigned long long d;
    asm("fma.rn.f32x2 %0, %1, %2, %3;" : "=l"(d) : "l"(a), "l"(b), "l"(c));
    return d;
}
__device__ __forceinline__ void unpack2(unsigned long long v, float& lo, float& hi) {
    unsigned l, h;
    asm("mov.b64 {%0, %1}, %2;" : "=r"(l), "=r"(h) : "l"(v));
    lo = __uint_as_float(l);
    hi = __uint_as_float(h);
}

// ---------------------------------------------------------------------------
// Tiled SGEMM: C[M,N] = A[M,K] @ op(B) (+ bias), 128x128 block, 8x8 microtile.
//   TRANSB=false: B is [K,N] row-major (ldb=N)
//   TRANSB=true : B is [N,K] row-major (ldb=K)  -> C = A @ B^T
// blockIdx.z = batch (strides sA/sB/sC in elements).
// All dims must be multiples of the tile sizes (true for this problem).
// ---------------------------------------------------------------------------
#define BM 128
#define BN 128
#define BKK 8

template<bool TRANSB, bool HAS_BIAS>
__global__ __launch_bounds__(256, 2)
void gemm128_kernel(const float* __restrict__ A, const float* __restrict__ B,
                    const float* __restrict__ bias, float* __restrict__ C,
                    int M, int N, int K,
                    long long sA, long long sB, long long sC)
{
    __shared__ float As[BKK][BM + 4];
    __shared__ float Bs[BKK][BN + 4];

    const int bz = blockIdx.z;
    A += (long long)bz * sA;
    B += (long long)bz * sB;
    C += (long long)bz * sC;

    const int tid = threadIdx.x;
    const int m0 = blockIdx.y * BM;
    const int n0 = blockIdx.x * BN;

    // A-style loads (128 rows x 8 k): row = tid>>1, k-offset = (tid&1)*4
    const int lr = tid >> 1;
    const int lc = (tid & 1) * 4;
    // NN B loads (8 k x 128 n): k = tid>>5, n-offset = (tid&31)*4
    const int brow = tid >> 5;
    const int bcol = (tid & 31) * 4;

    const int ty = tid >> 4;   // 0..15
    const int tx = tid & 15;   // 0..15

    unsigned long long acc[8][4];
    #pragma unroll
    for (int i = 0; i < 8; i++)
        #pragma unroll
        for (int j = 0; j < 4; j++) acc[i][j] = 0ULL;

    for (int k0 = 0; k0 < K; k0 += BKK) {
        // Load A tile (transposed into smem)
        float4 a4 = *(const float4*)&A[(long long)(m0 + lr) * K + k0 + lc];
        As[lc + 0][lr] = a4.x;
        As[lc + 1][lr] = a4.y;
        As[lc + 2][lr] = a4.z;
        As[lc + 3][lr] = a4.w;

        if (TRANSB) {
            float4 b4 = *(const float4*)&B[(long long)(n0 + lr) * K + k0 + lc];
            Bs[lc + 0][lr] = b4.x;
            Bs[lc + 1][lr] = b4.y;
            Bs[lc + 2][lr] = b4.z;
            Bs[lc + 3][lr] = b4.w;
        } else {
            float4 b4 = *(const float4*)&B[(long long)(k0 + brow) * N + n0 + bcol];
            *(float4*)&Bs[brow][bcol] = b4;
        }
        __syncthreads();

        #pragma unroll
        for (int kk = 0; kk < BKK; kk++) {
            // B pairs come straight out of LDS.128 as packed u64s
            ulonglong2 bq0 = *(const ulonglong2*)&Bs[kk][tx * 4];
            ulonglong2 bq1 = *(const ulonglong2*)&Bs[kk][64 + tx * 4];
            unsigned long long bp0 = bq0.x, bp1 = bq0.y, bp2 = bq1.x, bp3 = bq1.y;

            float4 a0 = *(const float4*)&As[kk][ty * 4];
            float4 a1 = *(const float4*)&As[kk][64 + ty * 4];
            float av[8] = {a0.x, a0.y, a0.z, a0.w, a1.x, a1.y, a1.z, a1.w};

            #pragma unroll
            for (int i = 0; i < 8; i++) {
                unsigned long long ap = pack2_dup(av[i]);
                acc[i][0] = fma2(ap, bp0, acc[i][0]);
                acc[i][1] = fma2(ap, bp1, acc[i][1]);
                acc[i][2] = fma2(ap, bp2, acc[i][2]);
                acc[i][3] = fma2(ap, bp3, acc[i][3]);
            }
        }
        __syncthreads();
    }

    // Epilogue
    const int c0 = n0 + tx * 4;
    const int c1 = n0 + 64 + tx * 4;
    float bv[8] = {0, 0, 0, 0, 0, 0, 0, 0};
    if (HAS_BIAS) {
        bv[0] = bias[c0];     bv[1] = bias[c0 + 1];
        bv[2] = bias[c0 + 2]; bv[3] = bias[c0 + 3];
        bv[4] = bias[c1];     bv[5] = bias[c1 + 1];
        bv[6] = bias[c1 + 2]; bv[7] = bias[c1 + 3];
    }

    #pragma unroll
    for (int i = 0; i < 8; i++) {
        int r = m0 + ((i < 4) ? (ty * 4 + i) : (64 + ty * 4 + (i - 4)));
        float o[8];
        #pragma unroll
        for (int j = 0; j < 4; j++) unpack2(acc[i][j], o[j * 2], o[j * 2 + 1]);
        if (HAS_BIAS) {
            #pragma unroll
            for (int j = 0; j < 8; j++) o[j] += bv[j];
        }
        *(float4*)&C[(long long)r * N + c0] = make_float4(o[0], o[1], o[2], o[3]);
        *(float4*)&C[(long long)r * N + c1] = make_float4(o[4], o[5], o[6], o[7]);
    }
}

// ---------------------------------------------------------------------------
// Row softmax over S_=2048 elements, with query-row multiplicative mask and
// the (non-standard) post-softmax NORM scale folded in.
//   mask[row]==0 -> scores row becomes all-zero -> softmax = uniform 1/S.
// One block (256 threads) per row; 8 elements per thread.
// ---------------------------------------------------------------------------
__global__ __launch_bounds__(256)
void softmax_mask_kernel(const int* __restrict__ mask, float* __restrict__ S)
{
    const int row = blockIdx.x;                 // 0..16383 == b*2048+s
    float* p = S + (long long)row * S_;
    const int tid = threadIdx.x;

    __shared__ float sred[8];

    float v[8];
    float mx = -3.0e38f;
    #pragma unroll
    for (int i = 0; i < 8; i++) {
        v[i] = p[tid + i * 256];
        mx = fmaxf(mx, v[i]);
    }
    #pragma unroll
    for (int o = 16; o; o >>= 1) mx = fmaxf(mx, __shfl_xor_sync(0xffffffffu, mx, o));
    if ((tid & 31) == 0) sred[tid >> 5] = mx;
    __syncthreads();
    float rowmax = sred[0];
    #pragma unroll
    for (int w = 1; w < 8; w++) rowmax = fmaxf(rowmax, sred[w]);
    __syncthreads();

    float s = 0.f;
    #pragma unroll
    for (int i = 0; i < 8; i++) {
        v[i] = __expf(v[i] - rowmax);
        s += v[i];
    }
    #pragma unroll
    for (int o = 16; o; o >>= 1) s += __shfl_xor_sync(0xffffffffu, s, o);
    if ((tid & 31) == 0) sred[tid >> 5] = s;
    __syncthreads();
    float rowsum = 0.f;
    #pragma unroll
    for (int w = 0; w < 8; w++) rowsum += sred[w];

    const int mk = mask[row];
    if (mk == 0) {
        const float u = NORM_CONST / (float)S_;
        #pragma unroll
        for (int i = 0; i < 8; i++) p[tid + i * 256] = u;
    } else {
        const float scale = NORM_CONST / rowsum;
        #pragma unroll
        for (int i = 0; i < 8; i++) p[tid + i * 256] = v[i] * scale;
    }
}

// ---------------------------------------------------------------------------
// Launch
// Inputs (metadata order): 0:x 1:mask 2:Wq 3:bq 4:Wk 5:bk 6:Wv 7:bv
// Output: [B,S,768] float32
// ---------------------------------------------------------------------------
extern "C" void kernel_launch(void* const* d_in, const int* in_sizes, int n_in,
                              void* d_out, int out_size)
{
    const float* x    = (const float*)d_in[0];
    const int*   mask = (const int*)  d_in[1];
    const float* Wq   = (const float*)d_in[2];
    const float* bq   = (const float*)d_in[3];
    const float* Wk   = (const float*)d_in[4];
    const float* bk   = (const float*)d_in[5];
    const float* Wv   = (const float*)d_in[6];
    const float* bv   = (const float*)d_in[7];
    float* out = (float*)d_out;

    float *pQ, *pK, *pV, *pS;
    cudaGetSymbolAddress((void**)&pQ, g_Q);
    cudaGetSymbolAddress((void**)&pK, g_K);
    cudaGetSymbolAddress((void**)&pV, g_V);
    cudaGetSymbolAddress((void**)&pS, g_S);

    dim3 blk(256);

    // 1) Projections: [16384,768] @ [768,768] + bias
    {
        dim3 grid(D_ / BN, M_TOT / BM, 1);
        gemm128_kernel<false, true><<<grid, blk>>>(x, Wq, bq, pQ, M_TOT, D_, D_, 0, 0, 0);
        gemm128_kernel<false, true><<<grid, blk>>>(x, Wk, bk, pK, M_TOT, D_, D_, 0, 0, 0);
        gemm128_kernel<false, true><<<grid, blk>>>(x, Wv, bv, pV, M_TOT, D_, D_, 0, 0, 0);
    }

    // 2) scores[b] = Q[b] @ K[b]^T  : [2048,768] x [2048,768]^T -> [2048,2048]
    {
        dim3 grid(S_ / BN, S_ / BM, B_);
        gemm128_kernel<true, false><<<grid, blk>>>(
            pQ, pK, nullptr, pS, S_, S_, D_,
            (long long)S_ * D_, (long long)S_ * D_, (long long)S_ * S_);
    }

    // 3) masked softmax (+ post-softmax NORM) over rows of scores
    softmax_mask_kernel<<<M_TOT, blk>>>(mask, pS);

    // 4) out[b] = attn[b] @ V[b] : [2048,2048] x [2048,768] -> [2048,768]
    {
        dim3 grid(D_ / BN, S_ / BM, B_);
        gemm128_kernel<false, false><<<grid, blk>>>(
            pS, pV, nullptr, out, S_, D_, S_,
            (long long)S_ * S_, (long long)S_ * D_, (long long)S_ * D_);
    }
}

// round 4
// speedup vs baseline: 1.8305x; 1.8305x over previous
#include <cuda_runtime.h>
#include <cuda_bf16.h>
#include <cstdint>

// ---------------------------------------------------------------------------
// SelfAttention B=8,S=2048,D=768 via baseline-PTX HMMA (mma.sync m16n8k16 bf16)
// split-bf16: A*B ~= Ah*Bh + Ah*Bl + Al*Bh  (fp32 accumulate, err ~2^-17)
// All GEMMs have the uniform form D[m][n] = sum_k A[m][k] * B[n][k].
// ---------------------------------------------------------------------------

#define B_   8
#define S_   2048
#define D_   768
#define MTOT (B_ * S_)                     // 16384
#define NORM_CONST 0.036084391824351615f   // 1/sqrt(768)

// ------------------------------ scratch ------------------------------------
__device__ __align__(256) __nv_bfloat16 g_xh[MTOT * D_],  g_xl[MTOT * D_];
__device__ __align__(256) __nv_bfloat16 g_WqTh[D_ * D_],  g_WqTl[D_ * D_];
__device__ __align__(256) __nv_bfloat16 g_WkTh[D_ * D_],  g_WkTl[D_ * D_];
__device__ __align__(256) __nv_bfloat16 g_WvTh[D_ * D_],  g_WvTl[D_ * D_];
__device__ __align__(256) __nv_bfloat16 g_Qh[MTOT * D_],  g_Ql[MTOT * D_];
__device__ __align__(256) __nv_bfloat16 g_Kh[MTOT * D_],  g_Kl[MTOT * D_];
__device__ __align__(256) __nv_bfloat16 g_VTh[D_ * MTOT], g_VTl[D_ * MTOT];
__device__ __align__(256) float         g_S[(size_t)B_ * S_ * S_];
__device__ __align__(256) __nv_bfloat16 g_Ah[(size_t)B_ * S_ * S_];
__device__ __align__(256) __nv_bfloat16 g_Al[(size_t)B_ * S_ * S_];

// --------------------------- PTX helpers -----------------------------------
__device__ __forceinline__ uint32_t smem_to_u32(const void* p) {
    uint32_t a;
    asm("{ .reg .u64 t; cvta.to.shared.u64 t, %1; cvt.u32.u64 %0, t; }"
        : "=r"(a) : "l"(p));
    return a;
}

__device__ __forceinline__ void ldsm4(uint32_t* r, uint32_t addr) {
    asm volatile("ldmatrix.sync.aligned.m8n8.x4.shared.b16 {%0,%1,%2,%3}, [%4];"
                 : "=r"(r[0]), "=r"(r[1]), "=r"(r[2]), "=r"(r[3]) : "r"(addr));
}

__device__ __forceinline__ void mma_bf16(float* c, const uint32_t* a,
                                         uint32_t b0, uint32_t b1) {
    asm volatile(
        "mma.sync.aligned.m16n8k16.row.col.f32.bf16.bf16.f32 "
        "{%0,%1,%2,%3}, {%4,%5,%6,%7}, {%8,%9}, {%0,%1,%2,%3};"
        : "+f"(c[0]), "+f"(c[1]), "+f"(c[2]), "+f"(c[3])
        : "r"(a[0]), "r"(a[1]), "r"(a[2]), "r"(a[3]), "r"(b0), "r"(b1));
}

// ------------------------------ GEMM kernel --------------------------------
// Block tile 128x128, K-chunk 32 bf16. 8 warps = 4m x 2n, warp tile 32x64.
// smem tiles: Ah, Al, Bh, Bl; 128 rows x 32 bf16, row stride padded to 80 B
// (rows 0..7 land on distinct 16B slots mod 128B -> conflict-free ldmatrix).
#define BKC 32
#define ROWB 80
#define TILEB (128 * ROWB)                 // 10240 B per tile
#define STAGEB (4 * TILEB)                 // 40960 B per stage
#define GEMM_SMEM (2 * STAGEB)             // 81920 B

__device__ __forceinline__ void copy_stage(
    uint32_t st,
    const __nv_bfloat16* Ah, const __nv_bfloat16* Al, int lda,
    const __nv_bfloat16* Bh, const __nv_bfloat16* Bl, int ldb,
    int m0, int n0, int k0, int tid)
{
    const int rsel = tid >> 2;          // 0..63
    const int ch   = tid & 3;           // 16B chunk within 64B row
    #pragma unroll
    for (int j = 0; j < 8; j++) {
        const int tile = j >> 1;                       // compile-time
        const int rowL = ((j & 1) << 6) + rsel;        // 0..127
        const __nv_bfloat16* p = (tile == 0) ? Ah : (tile == 1) ? Al
                                : (tile == 2) ? Bh : Bl;
        const int ld   = (tile < 2) ? lda : ldb;
        const int rowG = ((tile < 2) ? m0 : n0) + rowL;
        const __nv_bfloat16* src = p + (long long)rowG * ld + k0 + ch * 8;
        uint32_t dst = st + tile * TILEB + rowL * ROWB + ch * 16;
        asm volatile("cp.async.cg.shared.global [%0], [%1], 16;"
                     :: "r"(dst), "l"(src) : "memory");
    }
}

// OUT_MODE: 0 = fp32 store; 1 = bf16 hi/lo store, bias[col]; 2 = bf16 hi/lo, bias[row]
template <int OUT_MODE>
__global__ __launch_bounds__(256, 1)
void mma_gemm_kernel(const __nv_bfloat16* __restrict__ Ah, const __nv_bfloat16* __restrict__ Al,
                     int lda, long long strideA,
                     const __nv_bfloat16* __restrict__ Bh, const __nv_bfloat16* __restrict__ Bl,
                     int ldb, long long strideB,
                     float* __restrict__ Cf,
                     __nv_bfloat16* __restrict__ Ch, __nv_bfloat16* __restrict__ Cl,
                     int ldc, long long strideC,
                     const float* __restrict__ bias, int Ktot)
{
    extern __shared__ char smem[];
    const uint32_t sb = smem_to_u32(smem);
    const int tid  = threadIdx.x;
    const int wid  = tid >> 5;
    const int lane = tid & 31;
    const int wm   = wid & 3;           // warp m index (0..3) -> 32 rows
    const int wn   = wid >> 2;          // warp n index (0..1) -> 64 cols
    const int m0 = blockIdx.y * 128;
    const int n0 = blockIdx.x * 128;
    const long long bz = blockIdx.z;

    Ah += bz * strideA;  Al += bz * strideA;
    Bh += bz * strideB;  Bl += bz * strideB;

    float acc[2][8][4];
    #pragma unroll
    for (int i = 0; i < 2; i++)
        #pragma unroll
        for (int j = 0; j < 8; j++)
            #pragma unroll
            for (int q = 0; q < 4; q++) acc[i][j][q] = 0.f;

    // ldmatrix lane addressing: row = lane%16, 16B half = lane/16
    const int lrow = lane & 15;
    const int lhalf = (lane >> 4) << 4;

    copy_stage(sb, Ah, Al, lda, Bh, Bl, ldb, m0, n0, 0, tid);
    asm volatile("cp.async.commit_group;" ::: "memory");

    const int NIT = Ktot / BKC;
    for (int it = 0; it < NIT; ++it) {
        const uint32_t st = sb + (it & 1) * STAGEB;
        if (it + 1 < NIT) {
            copy_stage(sb + ((it + 1) & 1) * STAGEB,
                       Ah, Al, lda, Bh, Bl, ldb, m0, n0, (it + 1) * BKC, tid);
            asm volatile("cp.async.commit_group;" ::: "memory");
            asm volatile("cp.async.wait_group 1;" ::: "memory");
        } else {
            asm volatile("cp.async.wait_group 0;" ::: "memory");
        }
        __syncthreads();

        #pragma unroll
        for (int ks = 0; ks < 2; ks++) {
            uint32_t ah[2][4], al[2][4], bh[4][4], bl[4][4];
            #pragma unroll
            for (int mf = 0; mf < 2; mf++) {
                uint32_t ra = st + (wm * 32 + mf * 16 + lrow) * ROWB + ks * 32 + lhalf;
                ldsm4(ah[mf], ra);
                ldsm4(al[mf], ra + TILEB);
            }
            #pragma unroll
            for (int nf2 = 0; nf2 < 4; nf2++) {
                uint32_t rb = st + 2 * TILEB
                            + (wn * 64 + nf2 * 16 + lrow) * ROWB + ks * 32 + lhalf;
                ldsm4(bh[nf2], rb);
                ldsm4(bl[nf2], rb + TILEB);
            }
            #pragma unroll
            for (int mf = 0; mf < 2; mf++) {
                #pragma unroll
                for (int nf = 0; nf < 8; nf++) {
                    const int g = nf >> 1, h = nf & 1;
                    mma_bf16(acc[mf][nf], ah[mf], bh[g][h], bh[g][2 + h]);
                    mma_bf16(acc[mf][nf], ah[mf], bl[g][h], bl[g][2 + h]);
                    mma_bf16(acc[mf][nf], al[mf], bh[g][h], bh[g][2 + h]);
                }
            }
        }
        __syncthreads();
    }

    // ----------------------------- epilogue --------------------------------
    const int rbase = m0 + wm * 32 + (lane >> 2);
    const int cbase = n0 + wn * 64 + (lane & 3) * 2;
    #pragma unroll
    for (int mf = 0; mf < 2; mf++) {
        #pragma unroll
        for (int nf = 0; nf < 8; nf++) {
            const int col = cbase + nf * 8;
            #pragma unroll
            for (int half = 0; half < 2; half++) {
                const int row = rbase + mf * 16 + half * 8;
                float v0 = acc[mf][nf][half * 2 + 0];
                float v1 = acc[mf][nf][half * 2 + 1];
                if (OUT_MODE == 0) {
                    float2* dst = (float2*)(Cf + bz * strideC
                                            + (long long)row * ldc + col);
                    *dst = make_float2(v0, v1);
                } else {
                    if (OUT_MODE == 1) { v0 += bias[col]; v1 += bias[col + 1]; }
                    else               { float rb2 = bias[row]; v0 += rb2; v1 += rb2; }
                    __nv_bfloat16 h0 = __float2bfloat16_rn(v0);
                    __nv_bfloat16 h1 = __float2bfloat16_rn(v1);
                    __nv_bfloat16 l0 = __float2bfloat16_rn(v0 - __bfloat162float(h0));
                    __nv_bfloat16 l1 = __float2bfloat16_rn(v1 - __bfloat162float(h1));
                    __nv_bfloat162 hp; hp.x = h0; hp.y = h1;
                    __nv_bfloat162 lp; lp.x = l0; lp.y = l1;
                    *(__nv_bfloat162*)(Ch + bz * strideC + (long long)row * ldc + col) = hp;
                    *(__nv_bfloat162*)(Cl + bz * strideC + (long long)row * ldc + col) = lp;
                }
            }
        }
    }
}

// ------------------------- elementwise kernels -----------------------------
__global__ __launch_bounds__(256)
void split_kernel(const float* __restrict__ x, __nv_bfloat16* __restrict__ h,
                  __nv_bfloat16* __restrict__ l, int n)
{
    int i = (blockIdx.x * 256 + threadIdx.x) * 4;
    if (i + 3 < n) {
        float4 v = *(const float4*)(x + i);
        float vv[4] = {v.x, v.y, v.z, v.w};
        #pragma unroll
        for (int q = 0; q < 4; q++) {
            __nv_bfloat16 hh = __float2bfloat16_rn(vv[q]);
            h[i + q] = hh;
            l[i + q] = __float2bfloat16_rn(vv[q] - __bfloat162float(hh));
        }
    }
}

__global__ __launch_bounds__(256)
void transpose_split_kernel(const float* __restrict__ W,
                            __nv_bfloat16* __restrict__ th, __nv_bfloat16* __restrict__ tl)
{
    int idx = blockIdx.x * 256 + threadIdx.x;
    if (idx < D_ * D_) {
        int j = idx / D_, i = idx - j * D_;
        float v = W[i * D_ + j];
        __nv_bfloat16 hh = __float2bfloat16_rn(v);
        th[idx] = hh;
        tl[idx] = __float2bfloat16_rn(v - __bfloat162float(hh));
    }
}

// ------------------------------ softmax ------------------------------------
__global__ __launch_bounds__(256)
void softmax_mask_kernel(const int* __restrict__ mask, const float* __restrict__ S,
                         __nv_bfloat16* __restrict__ Ah, __nv_bfloat16* __restrict__ Al)
{
    const long long row = blockIdx.x;
    const float* p = S + row * S_;
    __nv_bfloat16* ph = Ah + row * S_;
    __nv_bfloat16* pl = Al + row * S_;
    const int tid = threadIdx.x;
    __shared__ float sred[8];

    float v[8];
    float mx = -3.0e38f;
    #pragma unroll
    for (int i = 0; i < 8; i++) { v[i] = p[tid + i * 256]; mx = fmaxf(mx, v[i]); }
    #pragma unroll
    for (int o = 16; o; o >>= 1) mx = fmaxf(mx, __shfl_xor_sync(0xffffffffu, mx, o));
    if ((tid & 31) == 0) sred[tid >> 5] = mx;
    __syncthreads();
    float rowmax = sred[0];
    #pragma unroll
    for (int w = 1; w < 8; w++) rowmax = fmaxf(rowmax, sred[w]);
    __syncthreads();

    float s = 0.f;
    #pragma unroll
    for (int i = 0; i < 8; i++) { v[i] = __expf(v[i] - rowmax); s += v[i]; }
    #pragma unroll
    for (int o = 16; o; o >>= 1) s += __shfl_xor_sync(0xffffffffu, s, o);
    if ((tid & 31) == 0) sred[tid >> 5] = s;
    __syncthreads();
    float rowsum = 0.f;
    #pragma unroll
    for (int w = 0; w < 8; w++) rowsum += sred[w];

    const float scale = (mask[row] == 0) ? 0.0f : (NORM_CONST / rowsum);
    const float unif  = NORM_CONST / (float)S_;
    #pragma unroll
    for (int i = 0; i < 8; i++) {
        float a = (mask[row] == 0) ? unif : v[i] * scale;
        __nv_bfloat16 hh = __float2bfloat16_rn(a);
        ph[tid + i * 256] = hh;
        pl[tid + i * 256] = __float2bfloat16_rn(a - __bfloat162float(hh));
    }
}

// ------------------------------- launch ------------------------------------
extern "C" void kernel_launch(void* const* d_in, const int* in_sizes, int n_in,
                              void* d_out, int out_size)
{
    const float* x    = (const float*)d_in[0];
    const int*   mask = (const int*)  d_in[1];
    const float* Wq   = (const float*)d_in[2];
    const float* bq   = (const float*)d_in[3];
    const float* Wk   = (const float*)d_in[4];
    const float* bk   = (const float*)d_in[5];
    const float* Wv   = (const float*)d_in[6];
    const float* bv   = (const float*)d_in[7];
    float* out = (float*)d_out;

    __nv_bfloat16 *xh, *xl, *WqTh, *WqTl, *WkTh, *WkTl, *WvTh, *WvTl;
    __nv_bfloat16 *Qh, *Ql, *Kh, *Kl, *VTh, *VTl, *Atth, *Attl;
    float* Sc;
    cudaGetSymbolAddress((void**)&xh, g_xh);     cudaGetSymbolAddress((void**)&xl, g_xl);
    cudaGetSymbolAddress((void**)&WqTh, g_WqTh); cudaGetSymbolAddress((void**)&WqTl, g_WqTl);
    cudaGetSymbolAddress((void**)&WkTh, g_WkTh); cudaGetSymbolAddress((void**)&WkTl, g_WkTl);
    cudaGetSymbolAddress((void**)&WvTh, g_WvTh); cudaGetSymbolAddress((void**)&WvTl, g_WvTl);
    cudaGetSymbolAddress((void**)&Qh, g_Qh);     cudaGetSymbolAddress((void**)&Ql, g_Ql);
    cudaGetSymbolAddress((void**)&Kh, g_Kh);     cudaGetSymbolAddress((void**)&Kl, g_Kl);
    cudaGetSymbolAddress((void**)&VTh, g_VTh);   cudaGetSymbolAddress((void**)&VTl, g_VTl);
    cudaGetSymbolAddress((void**)&Sc, g_S);
    cudaGetSymbolAddress((void**)&Atth, g_Ah);   cudaGetSymbolAddress((void**)&Attl, g_Al);

    cudaFuncSetAttribute(mma_gemm_kernel<0>, cudaFuncAttributeMaxDynamicSharedMemorySize, GEMM_SMEM);
    cudaFuncSetAttribute(mma_gemm_kernel<1>, cudaFuncAttributeMaxDynamicSharedMemorySize, GEMM_SMEM);
    cudaFuncSetAttribute(mma_gemm_kernel<2>, cudaFuncAttributeMaxDynamicSharedMemorySize, GEMM_SMEM);

    dim3 blk(256);

    // 0) splits
    split_kernel<<<(MTOT * D_ / 4 + 255) / 256, blk>>>(x, xh, xl, MTOT * D_);
    transpose_split_kernel<<<(D_ * D_ + 255) / 256, blk>>>(Wq, WqTh, WqTl);
    transpose_split_kernel<<<(D_ * D_ + 255) / 256, blk>>>(Wk, WkTh, WkTl);
    transpose_split_kernel<<<(D_ * D_ + 255) / 256, blk>>>(Wv, WvTh, WvTl);

    // 1) Q/K projections: A=x[16384,768], B=W^T[768,768] -> split bf16 out
    {
        dim3 grid(D_ / 128, MTOT / 128, 1);
        mma_gemm_kernel<1><<<grid, blk, GEMM_SMEM>>>(
            xh, xl, D_, 0, WqTh, WqTl, D_, 0,
            nullptr, Qh, Ql, D_, 0, bq, D_);
        mma_gemm_kernel<1><<<grid, blk, GEMM_SMEM>>>(
            xh, xl, D_, 0, WkTh, WkTl, D_, 0,
            nullptr, Kh, Kl, D_, 0, bk, D_);
    }
    // 2) V^T = WvT @ x^T : A=WvT[768,768], B=x[16384,768] -> VT[768,16384] split
    {
        dim3 grid(MTOT / 128, D_ / 128, 1);
        mma_gemm_kernel<2><<<grid, blk, GEMM_SMEM>>>(
            WvTh, WvTl, D_, 0, xh, xl, D_, 0,
            nullptr, VTh, VTl, MTOT, 0, bv, D_);
    }
    // 3) scores[b] = Q[b] @ K[b]^T -> fp32 [2048,2048]
    {
        dim3 grid(S_ / 128, S_ / 128, B_);
        mma_gemm_kernel<0><<<grid, blk, GEMM_SMEM>>>(
            Qh, Ql, D_, (long long)S_ * D_,
            Kh, Kl, D_, (long long)S_ * D_,
            Sc, nullptr, nullptr, S_, (long long)S_ * S_, nullptr, D_);
    }
    // 4) masked softmax + NORM -> attn hi/lo bf16
    softmax_mask_kernel<<<MTOT, blk>>>(mask, Sc, Atth, Attl);

    // 5) out[b] = attn[b] @ V[b] : A=attn[2048,2048], B=VT rows=d, ld=MTOT
    {
        dim3 grid(D_ / 128, S_ / 128, B_);
        mma_gemm_kernel<0><<<grid, blk, GEMM_SMEM>>>(
            Atth, Attl, S_, (long long)S_ * S_,
            VTh, VTl, MTOT, (long long)S_,
            out, nullptr, nullptr, D_, (long long)S_ * D_, nullptr, S_);
    }
}

// round 6
// speedup vs baseline: 2.8500x; 1.5569x over previous
#include <cuda_runtime.h>
#include <cuda_bf16.h>
#include <cstdint>

// ---------------------------------------------------------------------------
// SelfAttention B=8,S=2048,D=768 via mma.sync m16n8k16 bf16, split-bf16 3-term
// + mask-driven row compaction: masked query rows (~50%) produce constant
//   output NORM*mean(V[b]); scores/softmax/attnV computed only for unmasked.
// ---------------------------------------------------------------------------

#define B_   8
#define S_   2048
#define D_   768
#define MTOT (B_ * S_)                     // 16384
#define NORM_CONST 0.036084391824351615f   // 1/sqrt(768)

// ------------------------------ scratch ------------------------------------
__device__ __align__(256) __nv_bfloat16 g_xh[MTOT * D_],  g_xl[MTOT * D_];
__device__ __align__(256) __nv_bfloat16 g_WqTh[D_ * D_],  g_WqTl[D_ * D_];
__device__ __align__(256) __nv_bfloat16 g_WkTh[D_ * D_],  g_WkTl[D_ * D_];
__device__ __align__(256) __nv_bfloat16 g_WvTh[D_ * D_],  g_WvTl[D_ * D_];
__device__ __align__(256) __nv_bfloat16 g_Qh[MTOT * D_],  g_Ql[MTOT * D_];   // compacted
__device__ __align__(256) __nv_bfloat16 g_Kh[MTOT * D_],  g_Kl[MTOT * D_];
__device__ __align__(256) __nv_bfloat16 g_VTh[D_ * MTOT], g_VTl[D_ * MTOT];
__device__ __align__(256) float         g_S[(size_t)B_ * S_ * S_];
__device__ __align__(256) __nv_bfloat16 g_Ah[(size_t)B_ * S_ * S_];
__device__ __align__(256) __nv_bfloat16 g_Al[(size_t)B_ * S_ * S_];
__device__ int   g_cnt[B_];           // unmasked rows per batch
__device__ int   g_c2o[MTOT];         // compacted slot -> global orig row (-1 pad)
__device__ int   g_o2s[MTOT];         // global orig row -> within-batch slot (-1 masked)
__device__ float g_mv[B_ * D_];       // NORM * mean_t V[b,t,:]

// --------------------------- PTX helpers -----------------------------------
__device__ __forceinline__ uint32_t smem_to_u32(const void* p) {
    uint32_t a;
    asm("{ .reg .u64 t; cvta.to.shared.u64 t, %1; cvt.u32.u64 %0, t; }"
        : "=r"(a) : "l"(p));
    return a;
}

__device__ __forceinline__ void ldsm4(uint32_t* r, uint32_t addr) {
    asm volatile("ldmatrix.sync.aligned.m8n8.x4.shared.b16 {%0,%1,%2,%3}, [%4];"
                 : "=r"(r[0]), "=r"(r[1]), "=r"(r[2]), "=r"(r[3]) : "r"(addr));
}

__device__ __forceinline__ void mma_bf16(float* c, const uint32_t* a,
                                         uint32_t b0, uint32_t b1) {
    asm volatile(
        "mma.sync.aligned.m16n8k16.row.col.f32.bf16.bf16.f32 "
        "{%0,%1,%2,%3}, {%4,%5,%6,%7}, {%8,%9}, {%0,%1,%2,%3};"
        : "+f"(c[0]), "+f"(c[1]), "+f"(c[2]), "+f"(c[3])
        : "r"(a[0]), "r"(a[1]), "r"(a[2]), "r"(a[3]), "r"(b0), "r"(b1));
}

// ------------------------------ GEMM kernel --------------------------------
// Block tile 128x128, K-chunk 32 bf16, 8 warps (4m x 2n), warp tile 32x64.
// smem: Ah, Al, Bh, Bl tiles; 128 rows x 32 bf16, row stride 80 B (conflict-free).
#define BKC 32
#define ROWB 80
#define TILEB (128 * ROWB)                 // 10240 B
#define STAGEB (4 * TILEB)                 // 40960 B
#define GEMM_SMEM (2 * STAGEB)             // 81920 B -> 2 CTAs/SM

__device__ __forceinline__ void copy_stage(
    uint32_t st,
    const __nv_bfloat16* Ah, const __nv_bfloat16* Al, int lda,
    const __nv_bfloat16* Bh, const __nv_bfloat16* Bl, int ldb,
    int m0, int n0, int k0, int tid)
{
    const int rsel = tid >> 2;
    const int ch   = tid & 3;
    #pragma unroll
    for (int j = 0; j < 8; j++) {
        const int tile = j >> 1;
        const int rowL = ((j & 1) << 6) + rsel;
        const __nv_bfloat16* p = (tile == 0) ? Ah : (tile == 1) ? Al
                                : (tile == 2) ? Bh : Bl;
        const int ld   = (tile < 2) ? lda : ldb;
        const int rowG = ((tile < 2) ? m0 : n0) + rowL;
        const __nv_bfloat16* src = p + (long long)rowG * ld + k0 + ch * 8;
        uint32_t dst = st + tile * TILEB + rowL * ROWB + ch * 16;
        asm volatile("cp.async.cg.shared.global [%0], [%1], 16;"
                     :: "r"(dst), "l"(src) : "memory");
    }
}

// OUT_MODE: 0 fp32 direct | 1 bf16split bias[col] | 2 bf16split bias[row]
//           3 bf16split bias[col] + scatter rows via o2s (Q proj)
//           4 fp32 + scatter rows via c2o (attnV -> out)
template <int OUT_MODE>
__global__ __launch_bounds__(256, 2)
void mma_gemm_kernel(const __nv_bfloat16* __restrict__ Ah, const __nv_bfloat16* __restrict__ Al,
                     int lda, long long strideA,
                     const __nv_bfloat16* __restrict__ Bh, const __nv_bfloat16* __restrict__ Bl,
                     int ldb, long long strideB,
                     float* __restrict__ Cf,
                     __nv_bfloat16* __restrict__ Ch, __nv_bfloat16* __restrict__ Cl,
                     int ldc, long long strideC,
                     const float* __restrict__ bias, int Ktot,
                     const int* __restrict__ cntp, const int* __restrict__ rowmap)
{
    const long long bz = blockIdx.z;
    const int m0 = blockIdx.y * 128;
    if (cntp && m0 >= cntp[bz]) return;          // whole m-tile masked out
    const int n0 = blockIdx.x * 128;

    extern __shared__ char smem[];
    const uint32_t sb = smem_to_u32(smem);
    const int tid  = threadIdx.x;
    const int wid  = tid >> 5;
    const int lane = tid & 31;
    const int wm   = wid & 3;
    const int wn   = wid >> 2;

    Ah += bz * strideA;  Al += bz * strideA;
    Bh += bz * strideB;  Bl += bz * strideB;

    float acc[2][8][4];
    #pragma unroll
    for (int i = 0; i < 2; i++)
        #pragma unroll
        for (int j = 0; j < 8; j++)
            #pragma unroll
            for (int q = 0; q < 4; q++) acc[i][j][q] = 0.f;

    const int lrow  = lane & 15;
    const int lhalf = (lane >> 4) << 4;

    copy_stage(sb, Ah, Al, lda, Bh, Bl, ldb, m0, n0, 0, tid);
    asm volatile("cp.async.commit_group;" ::: "memory");

    const int NIT = Ktot / BKC;
    for (int it = 0; it < NIT; ++it) {
        const uint32_t st = sb + (it & 1) * STAGEB;
        __syncthreads();                          // readers of other stage done
        if (it + 1 < NIT) {
            copy_stage(sb + ((it + 1) & 1) * STAGEB,
                       Ah, Al, lda, Bh, Bl, ldb, m0, n0, (it + 1) * BKC, tid);
            asm volatile("cp.async.commit_group;" ::: "memory");
            asm volatile("cp.async.wait_group 1;" ::: "memory");
        } else {
            asm volatile("cp.async.wait_group 0;" ::: "memory");
        }
        __syncthreads();

        #pragma unroll
        for (int ks = 0; ks < 2; ks++) {
            uint32_t afh[2][4], afl[2][4], bf[4][4];
            #pragma unroll
            for (int mf = 0; mf < 2; mf++) {
                uint32_t ra = st + (wm * 32 + mf * 16 + lrow) * ROWB + ks * 32 + lhalf;
                ldsm4(afh[mf], ra);
                ldsm4(afl[mf], ra + TILEB);
            }
            uint32_t rbb[4];
            #pragma unroll
            for (int g = 0; g < 4; g++) {
                rbb[g] = st + 2 * TILEB + (wn * 64 + g * 16 + lrow) * ROWB + ks * 32 + lhalf;
                ldsm4(bf[g], rbb[g]);                     // Bh
            }
            #pragma unroll
            for (int mf = 0; mf < 2; mf++)
                #pragma unroll
                for (int nf = 0; nf < 8; nf++) {
                    const int g = nf >> 1, h = nf & 1;
                    mma_bf16(acc[mf][nf], afh[mf], bf[g][h], bf[g][2 + h]);
                    mma_bf16(acc[mf][nf], afl[mf], bf[g][h], bf[g][2 + h]);
                }
            #pragma unroll
            for (int g = 0; g < 4; g++)
                ldsm4(bf[g], rbb[g] + TILEB);             // Bl (reuse regs)
            #pragma unroll
            for (int mf = 0; mf < 2; mf++)
                #pragma unroll
                for (int nf = 0; nf < 8; nf++) {
                    const int g = nf >> 1, h = nf & 1;
                    mma_bf16(acc[mf][nf], afh[mf], bf[g][h], bf[g][2 + h]);
                }
        }
    }

    // ----------------------------- epilogue --------------------------------
    const int rbase = m0 + wm * 32 + (lane >> 2);
    const int cbase = n0 + wn * 64 + (lane & 3) * 2;
    #pragma unroll
    for (int mf = 0; mf < 2; mf++) {
        #pragma unroll
        for (int half = 0; half < 2; half++) {
            const int row = rbase + mf * 16 + half * 8;   // local (within batch tile-space)
            int drow = row;                                // dest row (global for 3/4)
            if (OUT_MODE == 3) {
                int slot = rowmap[row];                    // proj: row is global
                if (slot < 0) continue;
                drow = (row & ~(S_ - 1)) + slot;
            } else if (OUT_MODE == 4) {
                drow = rowmap[bz * S_ + row];
                if (drow < 0) continue;
            }
            #pragma unroll
            for (int nf = 0; nf < 8; nf++) {
                const int col = cbase + nf * 8;
                float v0 = acc[mf][nf][half * 2 + 0];
                float v1 = acc[mf][nf][half * 2 + 1];
                if (OUT_MODE == 0) {
                    *(float2*)(Cf + bz * strideC + (long long)drow * ldc + col)
                        = make_float2(v0, v1);
                } else if (OUT_MODE == 4) {
                    *(float2*)(Cf + (long long)drow * ldc + col) = make_float2(v0, v1);
                } else {
                    if (OUT_MODE == 2) { float rb2 = bias[row]; v0 += rb2; v1 += rb2; }
                    else               { v0 += bias[col]; v1 += bias[col + 1]; }
                    __nv_bfloat16 h0 = __float2bfloat16_rn(v0);
                    __nv_bfloat16 h1 = __float2bfloat16_rn(v1);
                    __nv_bfloat16 l0 = __float2bfloat16_rn(v0 - __bfloat162float(h0));
                    __nv_bfloat16 l1 = __float2bfloat16_rn(v1 - __bfloat162float(h1));
                    __nv_bfloat162 hp; hp.x = h0; hp.y = h1;
                    __nv_bfloat162 lp; lp.x = l0; lp.y = l1;
                    *(__nv_bfloat162*)(Ch + bz * strideC + (long long)drow * ldc + col) = hp;
                    *(__nv_bfloat162*)(Cl + bz * strideC + (long long)drow * ldc + col) = lp;
                }
            }
        }
    }
}

// --------------------------- compaction ------------------------------------
// One block per batch. Stable compaction of unmasked rows.
__global__ __launch_bounds__(256)
void compact_kernel(const int* __restrict__ mask, int* __restrict__ cnt,
                    int* __restrict__ c2o, int* __restrict__ o2s)
{
    const int b = blockIdx.x, tid = threadIdx.x;
    const int lane = tid & 31, wid = tid >> 5;
    const int* m = mask + b * S_;
    __shared__ int wsum[8];
    __shared__ int s_tot;

    int loc[8], c = 0;
    #pragma unroll
    for (int i = 0; i < 8; i++) { loc[i] = (m[tid * 8 + i] != 0); c += loc[i]; }
    int pre = c;
    #pragma unroll
    for (int o = 1; o < 32; o <<= 1) {
        int v = __shfl_up_sync(0xffffffffu, pre, o);
        if (lane >= o) pre += v;
    }
    if (lane == 31) wsum[wid] = pre;
    __syncthreads();
    int wbase = 0;
    for (int w = 0; w < wid; w++) wbase += wsum[w];
    int slot = wbase + pre - c;
    #pragma unroll
    for (int i = 0; i < 8; i++) {
        int s = tid * 8 + i;
        if (loc[i]) { c2o[b * S_ + slot] = b * S_ + s; o2s[b * S_ + s] = slot; slot++; }
        else        { o2s[b * S_ + s] = -1; }
    }
    if (tid == 0) {
        int tot = 0;
        for (int w = 0; w < 8; w++) tot += wsum[w];
        cnt[b] = tot;
        s_tot = tot;
    }
    __syncthreads();
    for (int s = s_tot + tid; s < S_; s += 256) c2o[b * S_ + s] = -1;
}

// ------------------------- elementwise kernels -----------------------------
__global__ __launch_bounds__(256)
void split_kernel(const float* __restrict__ x, __nv_bfloat16* __restrict__ h,
                  __nv_bfloat16* __restrict__ l, int n)
{
    int i = (blockIdx.x * 256 + threadIdx.x) * 4;
    if (i + 3 < n) {
        float4 v = *(const float4*)(x + i);
        float vv[4] = {v.x, v.y, v.z, v.w};
        #pragma unroll
        for (int q = 0; q < 4; q++) {
            __nv_bfloat16 hh = __float2bfloat16_rn(vv[q]);
            h[i + q] = hh;
            l[i + q] = __float2bfloat16_rn(vv[q] - __bfloat162float(hh));
        }
    }
}

// merged transpose+split of the three 768x768 weights
__global__ __launch_bounds__(256)
void transpose_split3_kernel(const float* __restrict__ Wq, const float* __restrict__ Wk,
                             const float* __restrict__ Wv,
                             __nv_bfloat16* __restrict__ qh, __nv_bfloat16* __restrict__ ql,
                             __nv_bfloat16* __restrict__ kh, __nv_bfloat16* __restrict__ kl,
                             __nv_bfloat16* __restrict__ vh, __nv_bfloat16* __restrict__ vl)
{
    int idx = blockIdx.x * 256 + threadIdx.x;
    if (idx >= D_ * D_) return;
    int j = idx / D_, i = idx - j * D_;
    const float* W = (blockIdx.y == 0) ? Wq : (blockIdx.y == 1) ? Wk : Wv;
    __nv_bfloat16* th = (blockIdx.y == 0) ? qh : (blockIdx.y == 1) ? kh : vh;
    __nv_bfloat16* tl = (blockIdx.y == 0) ? ql : (blockIdx.y == 1) ? kl : vl;
    float v = W[i * D_ + j];
    __nv_bfloat16 hh = __float2bfloat16_rn(v);
    th[idx] = hh;
    tl[idx] = __float2bfloat16_rn(v - __bfloat162float(hh));
}

// per-batch NORM*mean_t V[b,t,d] from VT (hi+lo), one block per (d, b)
__global__ __launch_bounds__(256)
void vmean_kernel(const __nv_bfloat16* __restrict__ vth,
                  const __nv_bfloat16* __restrict__ vtl, float* __restrict__ mv)
{
    const int d = blockIdx.x, b = blockIdx.y, tid = threadIdx.x;
    const __nv_bfloat16* ph = vth + (long long)d * MTOT + b * S_;
    const __nv_bfloat16* pl = vtl + (long long)d * MTOT + b * S_;
    float s = 0.f;
    #pragma unroll
    for (int i = 0; i < 8; i++) {
        int t = tid + i * 256;
        s += __bfloat162float(ph[t]) + __bfloat162float(pl[t]);
    }
    #pragma unroll
    for (int o = 16; o; o >>= 1) s += __shfl_xor_sync(0xffffffffu, s, o);
    __shared__ float ws[8];
    if ((tid & 31) == 0) ws[tid >> 5] = s;
    __syncthreads();
    if (tid == 0) {
        float t = 0.f;
        for (int w = 0; w < 8; w++) t += ws[w];
        mv[b * D_ + d] = t * (NORM_CONST / (float)S_);
    }
}

// fill masked rows of out with mv[b]
__global__ __launch_bounds__(256)
void fill_masked_kernel(const int* __restrict__ mask, const float* __restrict__ mv,
                        float* __restrict__ out)
{
    const int row = blockIdx.x;
    if (mask[row] != 0) return;
    const int b = row >> 11, tid = threadIdx.x;
    #pragma unroll
    for (int i = 0; i < 3; i++) {
        int d = tid + i * 256;
        out[(long long)row * D_ + d] = mv[b * D_ + d];
    }
}

// ------------------------------ softmax ------------------------------------
// Compacted-row softmax; pad rows [cnt, ceil128(cnt)) zero-filled.
__global__ __launch_bounds__(256)
void softmax_kernel(const int* __restrict__ cnt, const float* __restrict__ S,
                    __nv_bfloat16* __restrict__ Ah, __nv_bfloat16* __restrict__ Al)
{
    const long long row = blockIdx.x;
    const int b = (int)(row >> 11), r = (int)(row & (S_ - 1));
    const int c = cnt[b];
    const int cpad = (c + 127) & ~127;
    if (r >= cpad) return;
    const int tid = threadIdx.x;
    __nv_bfloat16* ph = Ah + row * S_;
    __nv_bfloat16* pl = Al + row * S_;
    if (r >= c) {                                   // pad row -> zeros
        __nv_bfloat162 z; z.x = __float2bfloat16_rn(0.f); z.y = z.x;
        #pragma unroll
        for (int i = 0; i < 4; i++) {
            ((__nv_bfloat162*)ph)[tid + i * 256] = z;
            ((__nv_bfloat162*)pl)[tid + i * 256] = z;
        }
        return;
    }
    const float* p = S + row * S_;
    __shared__ float sred[8];

    float v[8];
    float mx = -3.0e38f;
    #pragma unroll
    for (int i = 0; i < 8; i++) { v[i] = p[tid + i * 256]; mx = fmaxf(mx, v[i]); }
    #pragma unroll
    for (int o = 16; o; o >>= 1) mx = fmaxf(mx, __shfl_xor_sync(0xffffffffu, mx, o));
    if ((tid & 31) == 0) sred[tid >> 5] = mx;
    __syncthreads();
    float rowmax = sred[0];
    #pragma unroll
    for (int w = 1; w < 8; w++) rowmax = fmaxf(rowmax, sred[w]);
    __syncthreads();

    float s = 0.f;
    #pragma unroll
    for (int i = 0; i < 8; i++) { v[i] = __expf(v[i] - rowmax); s += v[i]; }
    #pragma unroll
    for (int o = 16; o; o >>= 1) s += __shfl_xor_sync(0xffffffffu, s, o);
    if ((tid & 31) == 0) sred[tid >> 5] = s;
    __syncthreads();
    float rowsum = 0.f;
    #pragma unroll
    for (int w = 0; w < 8; w++) rowsum += sred[w];

    const float scale = NORM_CONST / rowsum;
    #pragma unroll
    for (int i = 0; i < 8; i++) {
        float a = v[i] * scale;
        __nv_bfloat16 hh = __float2bfloat16_rn(a);
        ph[tid + i * 256] = hh;
        pl[tid + i * 256] = __float2bfloat16_rn(a - __bfloat162float(hh));
    }
}

// ------------------------------- launch ------------------------------------
extern "C" void kernel_launch(void* const* d_in, const int* in_sizes, int n_in,
                              void* d_out, int out_size)
{
    const float* x    = (const float*)d_in[0];
    const int*   mask = (const int*)  d_in[1];
    const float* Wq   = (const float*)d_in[2];
    const float* bq   = (const float*)d_in[3];
    const float* Wk   = (const float*)d_in[4];
    const float* bk   = (const float*)d_in[5];
    const float* Wv   = (const float*)d_in[6];
    const float* bv   = (const float*)d_in[7];
    float* out = (float*)d_out;

    __nv_bfloat16 *xh, *xl, *WqTh, *WqTl, *WkTh, *WkTl, *WvTh, *WvTl;
    __nv_bfloat16 *Qh, *Ql, *Kh, *Kl, *VTh, *VTl, *Atth, *Attl;
    float *Sc, *mv;
    int *cnt, *c2o, *o2s;
    cudaGetSymbolAddress((void**)&xh, g_xh);     cudaGetSymbolAddress((void**)&xl, g_xl);
    cudaGetSymbolAddress((void**)&WqTh, g_WqTh); cudaGetSymbolAddress((void**)&WqTl, g_WqTl);
    cudaGetSymbolAddress((void**)&WkTh, g_WkTh); cudaGetSymbolAddress((void**)&WkTl, g_WkTl);
    cudaGetSymbolAddress((void**)&WvTh, g_WvTh); cudaGetSymbolAddress((void**)&WvTl, g_WvTl);
    cudaGetSymbolAddress((void**)&Qh, g_Qh);     cudaGetSymbolAddress((void**)&Ql, g_Ql);
    cudaGetSymbolAddress((void**)&Kh, g_Kh);     cudaGetSymbolAddress((void**)&Kl, g_Kl);
    cudaGetSymbolAddress((void**)&VTh, g_VTh);   cudaGetSymbolAddress((void**)&VTl, g_VTl);
    cudaGetSymbolAddress((void**)&Sc, g_S);
    cudaGetSymbolAddress((void**)&Atth, g_Ah);   cudaGetSymbolAddress((void**)&Attl, g_Al);
    cudaGetSymbolAddress((void**)&cnt, g_cnt);
    cudaGetSymbolAddress((void**)&c2o, g_c2o);   cudaGetSymbolAddress((void**)&o2s, g_o2s);
    cudaGetSymbolAddress((void**)&mv, g_mv);

    cudaFuncSetAttribute(mma_gemm_kernel<0>, cudaFuncAttributeMaxDynamicSharedMemorySize, GEMM_SMEM);
    cudaFuncSetAttribute(mma_gemm_kernel<1>, cudaFuncAttributeMaxDynamicSharedMemorySize, GEMM_SMEM);
    cudaFuncSetAttribute(mma_gemm_kernel<2>, cudaFuncAttributeMaxDynamicSharedMemorySize, GEMM_SMEM);
    cudaFuncSetAttribute(mma_gemm_kernel<3>, cudaFuncAttributeMaxDynamicSharedMemorySize, GEMM_SMEM);
    cudaFuncSetAttribute(mma_gemm_kernel<4>, cudaFuncAttributeMaxDynamicSharedMemorySize, GEMM_SMEM);

    dim3 blk(256);

    // 1) compaction
    compact_kernel<<<B_, blk>>>(mask, cnt, c2o, o2s);
    // 2) x split
    split_kernel<<<(MTOT * D_ / 4 + 255) / 256, blk>>>(x, xh, xl, MTOT * D_);
    // 3) weight transpose+split (merged)
    {
        dim3 g((D_ * D_ + 255) / 256, 3);
        transpose_split3_kernel<<<g, blk>>>(Wq, Wk, Wv, WqTh, WqTl, WkTh, WkTl, WvTh, WvTl);
    }
    // 4) Q proj (scatter to compacted), 5) K proj
    {
        dim3 grid(D_ / 128, MTOT / 128, 1);
        mma_gemm_kernel<3><<<grid, blk, GEMM_SMEM>>>(
            xh, xl, D_, 0, WqTh, WqTl, D_, 0,
            nullptr, Qh, Ql, D_, 0, bq, D_, nullptr, o2s);
        mma_gemm_kernel<1><<<grid, blk, GEMM_SMEM>>>(
            xh, xl, D_, 0, WkTh, WkTl, D_, 0,
            nullptr, Kh, Kl, D_, 0, bk, D_, nullptr, nullptr);
    }
    // 6) V^T proj (profiled launch under ncu -s 5 -c 1)
    {
        dim3 grid(MTOT / 128, D_ / 128, 1);
        mma_gemm_kernel<2><<<grid, blk, GEMM_SMEM>>>(
            WvTh, WvTl, D_, 0, xh, xl, D_, 0,
            nullptr, VTh, VTl, MTOT, 0, bv, D_, nullptr, nullptr);
    }
    // 7) scores = Qc @ K^T (early exit beyond cnt)
    {
        dim3 grid(S_ / 128, S_ / 128, B_);
        mma_gemm_kernel<0><<<grid, blk, GEMM_SMEM>>>(
            Qh, Ql, D_, (long long)S_ * D_,
            Kh, Kl, D_, (long long)S_ * D_,
            Sc, nullptr, nullptr, S_, (long long)S_ * S_, nullptr, D_, cnt, nullptr);
    }
    // 8) per-batch V mean
    {
        dim3 g(D_, B_);
        vmean_kernel<<<g, blk>>>(VTh, VTl, mv);
    }
    // 9) softmax on compacted rows (+pad zero-fill)
    softmax_kernel<<<MTOT, blk>>>(cnt, Sc, Atth, Attl);
    // 10) out(unmasked) = attn @ V, scatter rows via c2o (early exit beyond cnt)
    {
        dim3 grid(D_ / 128, S_ / 128, B_);
        mma_gemm_kernel<4><<<grid, blk, GEMM_SMEM>>>(
            Atth, Attl, S_, (long long)S_ * S_,
            VTh, VTl, MTOT, (long long)S_,
            out, nullptr, nullptr, D_, 0, nullptr, S_, cnt, c2o);
    }
    // 11) masked rows = NORM * mean(V[b])
    fill_masked_kernel<<<MTOT, blk>>>(mask, mv, out);
}

// round 7
// speedup vs baseline: 3.3456x; 1.1739x over previous
#include <cuda_runtime.h>
#include <cuda_bf16.h>
#include <cstdint>

// ---------------------------------------------------------------------------
// SelfAttention B=8,S=2048,D=768 via mma.sync m16n8k16 bf16, split-bf16 3-term
// + mask row compaction (masked query rows -> NORM*mean(V[b]))
// R7: XOR-swizzled smem, 3-stage cp.async pipeline (1 sync/chunk),
//     Q-projection computed only on compacted (unmasked) rows via gather.
// ---------------------------------------------------------------------------

#define B_   8
#define S_   2048
#define D_   768
#define MTOT (B_ * S_)                     // 16384
#define NORM_CONST 0.036084391824351615f   // 1/sqrt(768)

// ------------------------------ scratch ------------------------------------
__device__ __align__(256) __nv_bfloat16 g_xh[MTOT * D_],  g_xl[MTOT * D_];
__device__ __align__(256) __nv_bfloat16 g_WqTh[D_ * D_],  g_WqTl[D_ * D_];
__device__ __align__(256) __nv_bfloat16 g_WkTh[D_ * D_],  g_WkTl[D_ * D_];
__device__ __align__(256) __nv_bfloat16 g_WvTh[D_ * D_],  g_WvTl[D_ * D_];
__device__ __align__(256) __nv_bfloat16 g_Qh[MTOT * D_],  g_Ql[MTOT * D_];   // compacted
__device__ __align__(256) __nv_bfloat16 g_Kh[MTOT * D_],  g_Kl[MTOT * D_];
__device__ __align__(256) __nv_bfloat16 g_VTh[D_ * MTOT], g_VTl[D_ * MTOT];
__device__ __align__(256) float         g_S[(size_t)B_ * S_ * S_];
__device__ __align__(256) __nv_bfloat16 g_Ah[(size_t)B_ * S_ * S_];
__device__ __align__(256) __nv_bfloat16 g_Al[(size_t)B_ * S_ * S_];
__device__ int   g_cnt[B_];
__device__ int   g_c2o[MTOT];         // compacted slot -> global orig row (-1 pad)
__device__ int   g_o2s[MTOT];         // orig row -> within-batch slot (-1 masked)
__device__ float g_mv[B_ * D_];       // NORM * mean_t V[b,t,:]

// --------------------------- PTX helpers -----------------------------------
__device__ __forceinline__ uint32_t smem_to_u32(const void* p) {
    uint32_t a;
    asm("{ .reg .u64 t; cvta.to.shared.u64 t, %1; cvt.u32.u64 %0, t; }"
        : "=r"(a) : "l"(p));
    return a;
}

__device__ __forceinline__ void ldsm4(uint32_t* r, uint32_t addr) {
    asm volatile("ldmatrix.sync.aligned.m8n8.x4.shared.b16 {%0,%1,%2,%3}, [%4];"
                 : "=r"(r[0]), "=r"(r[1]), "=r"(r[2]), "=r"(r[3]) : "r"(addr));
}

__device__ __forceinline__ void mma_bf16(float* c, const uint32_t* a,
                                         uint32_t b0, uint32_t b1) {
    asm volatile(
        "mma.sync.aligned.m16n8k16.row.col.f32.bf16.bf16.f32 "
        "{%0,%1,%2,%3}, {%4,%5,%6,%7}, {%8,%9}, {%0,%1,%2,%3};"
        : "+f"(c[0]), "+f"(c[1]), "+f"(c[2]), "+f"(c[3])
        : "r"(a[0]), "r"(a[1]), "r"(a[2]), "r"(a[3]), "r"(b0), "r"(b1));
}

// Swizzled smem offset for (row 0..127, 16B-chunk 0..3) in a 128x64B tile.
// line = row/2 (128B); slot(3b) = ((row&1)<<2 | chunk) ^ (line&7). Conflict-free
// for ldmatrix over any 8 consecutive aligned rows (slots 0..7 all distinct).
__device__ __forceinline__ uint32_t swzoff(int row, int chunk) {
    int line = row >> 1;
    int slot = (((row & 1) << 2) | chunk) ^ (line & 7);
    return (uint32_t)((line << 7) + (slot << 4));
}

// ------------------------------ GEMM kernel --------------------------------
// Block tile 128x128, K-chunk 32 bf16, 8 warps (4m x 2n), warp tile 32x64.
// smem per stage: Ah, Al, Bh, Bl tiles, 128 rows x 64B, XOR swizzle.
#define BKC 32
#define TILEB (128 * 64)                   // 8192 B
#define STAGEB (4 * TILEB)                 // 32768 B
#define NSTAGE 3
#define GEMM_SMEM (NSTAGE * STAGEB)        // 98304 B -> 2 CTAs/SM

__device__ __forceinline__ void copy_stage(
    uint32_t st,
    const __nv_bfloat16* Ah, const __nv_bfloat16* Al, int lda,
    const __nv_bfloat16* Bh, const __nv_bfloat16* Bl, int ldb,
    int rowA0, int rowA1, int n0, int k0, int tid)
{
    const int rsel = tid >> 2;          // 0..63
    const int ch   = tid & 3;           // 16B chunk
    #pragma unroll
    for (int j = 0; j < 8; j++) {
        const int tile = j >> 1;
        const int half = j & 1;
        const int rowL = (half << 6) + rsel;
        const __nv_bfloat16* p = (tile == 0) ? Ah : (tile == 1) ? Al
                                : (tile == 2) ? Bh : Bl;
        const int ld   = (tile < 2) ? lda : ldb;
        const int rowG = (tile < 2) ? (half ? rowA1 : rowA0) : (n0 + rowL);
        const __nv_bfloat16* src = p + (long long)rowG * ld + k0 + ch * 8;
        uint32_t dst = st + tile * TILEB + swzoff(rowL, ch);
        asm volatile("cp.async.cg.shared.global [%0], [%1], 16;"
                     :: "r"(dst), "l"(src) : "memory");
    }
}

// OUT_MODE: 0 fp32 direct | 1 bf16split bias[col] | 2 bf16split bias[row]
//           3 bf16split bias[col], A rows gathered via c2o, compacted out (Q proj)
//           4 fp32, scatter rows via c2o (attnV -> out)
template <int OUT_MODE>
__global__ __launch_bounds__(256, 2)
void mma_gemm_kernel(const __nv_bfloat16* __restrict__ Ah, const __nv_bfloat16* __restrict__ Al,
                     int lda, long long strideA,
                     const __nv_bfloat16* __restrict__ Bh, const __nv_bfloat16* __restrict__ Bl,
                     int ldb, long long strideB,
                     float* __restrict__ Cf,
                     __nv_bfloat16* __restrict__ Ch, __nv_bfloat16* __restrict__ Cl,
                     int ldc, long long strideC,
                     const float* __restrict__ bias, int Ktot,
                     const int* __restrict__ cntp, const int* __restrict__ rowmap)
{
    const long long bz = blockIdx.z;
    const int m0 = blockIdx.y * 128;
    if (cntp && m0 >= cntp[bz]) return;
    const int n0 = blockIdx.x * 128;

    extern __shared__ char smem[];
    const uint32_t sb = smem_to_u32(smem);
    const int tid  = threadIdx.x;
    const int wid  = tid >> 5;
    const int lane = tid & 31;
    const int wm   = wid & 3;
    const int wn   = wid >> 2;

    Ah += bz * strideA;  Al += bz * strideA;
    Bh += bz * strideB;  Bl += bz * strideB;

    // A-row resolution (gather for mode 3)
    const int rsel = tid >> 2;
    int rowA0, rowA1;
    if (OUT_MODE == 3) {
        const int* gm = rowmap + bz * S_;
        int g0 = gm[m0 + rsel];
        int g1 = gm[m0 + 64 + rsel];
        rowA0 = (g0 < 0) ? 0 : g0;      // pad rows: harmless garbage
        rowA1 = (g1 < 0) ? 0 : g1;
    } else {
        rowA0 = m0 + rsel;
        rowA1 = rowA0 + 64;
    }

    float acc[2][8][4];
    #pragma unroll
    for (int i = 0; i < 2; i++)
        #pragma unroll
        for (int j = 0; j < 8; j++)
            #pragma unroll
            for (int q = 0; q < 4; q++) acc[i][j][q] = 0.f;

    const int lrow = lane & 15;

    const int NIT = Ktot / BKC;
    // prologue: chunks 0,1 -> stages 0,1
    copy_stage(sb, Ah, Al, lda, Bh, Bl, ldb, rowA0, rowA1, n0, 0, tid);
    asm volatile("cp.async.commit_group;" ::: "memory");
    copy_stage(sb + STAGEB, Ah, Al, lda, Bh, Bl, ldb, rowA0, rowA1, n0, BKC, tid);
    asm volatile("cp.async.commit_group;" ::: "memory");

    int stage = 0;
    for (int it = 0; it < NIT; ++it) {
        if (it + 1 < NIT) asm volatile("cp.async.wait_group 1;" ::: "memory");
        else              asm volatile("cp.async.wait_group 0;" ::: "memory");
        __syncthreads();

        if (it + 2 < NIT) {
            int ns = stage + 2; if (ns >= NSTAGE) ns -= NSTAGE;
            copy_stage(sb + ns * STAGEB, Ah, Al, lda, Bh, Bl, ldb,
                       rowA0, rowA1, n0, (it + 2) * BKC, tid);
            asm volatile("cp.async.commit_group;" ::: "memory");
        }

        const uint32_t st = sb + stage * STAGEB;
        #pragma unroll
        for (int ks = 0; ks < 2; ks++) {
            const int ckc = ks * 2 + (lane >> 4);
            uint32_t afh[2][4], afl[2][4], bf[4][4];
            #pragma unroll
            for (int mf = 0; mf < 2; mf++) {
                uint32_t ra = st + swzoff(wm * 32 + mf * 16 + lrow, ckc);
                ldsm4(afh[mf], ra);
                ldsm4(afl[mf], ra + TILEB);
            }
            uint32_t rbb[4];
            #pragma unroll
            for (int g = 0; g < 4; g++) {
                rbb[g] = st + 2 * TILEB + swzoff(wn * 64 + g * 16 + lrow, ckc);
                ldsm4(bf[g], rbb[g]);                     // Bh
            }
            #pragma unroll
            for (int mf = 0; mf < 2; mf++)
                #pragma unroll
                for (int nf = 0; nf < 8; nf++) {
                    const int g = nf >> 1, h = nf & 1;
                    mma_bf16(acc[mf][nf], afh[mf], bf[g][h], bf[g][2 + h]);
                    mma_bf16(acc[mf][nf], afl[mf], bf[g][h], bf[g][2 + h]);
                }
            #pragma unroll
            for (int g = 0; g < 4; g++)
                ldsm4(bf[g], rbb[g] + TILEB);             // Bl (reuse regs)
            #pragma unroll
            for (int mf = 0; mf < 2; mf++)
                #pragma unroll
                for (int nf = 0; nf < 8; nf++) {
                    const int g = nf >> 1, h = nf & 1;
                    mma_bf16(acc[mf][nf], afh[mf], bf[g][h], bf[g][2 + h]);
                }
        }
        stage = (stage + 1 == NSTAGE) ? 0 : stage + 1;
    }

    // ----------------------------- epilogue --------------------------------
    const int rbase = m0 + wm * 32 + (lane >> 2);
    const int cbase = n0 + wn * 64 + (lane & 3) * 2;
    #pragma unroll
    for (int mf = 0; mf < 2; mf++) {
        #pragma unroll
        for (int half = 0; half < 2; half++) {
            const int row = rbase + mf * 16 + half * 8;
            int drow = row;
            if (OUT_MODE == 4) {
                drow = rowmap[bz * S_ + row];
                if (drow < 0) continue;
            }
            #pragma unroll
            for (int nf = 0; nf < 8; nf++) {
                const int col = cbase + nf * 8;
                float v0 = acc[mf][nf][half * 2 + 0];
                float v1 = acc[mf][nf][half * 2 + 1];
                if (OUT_MODE == 0) {
                    *(float2*)(Cf + bz * strideC + (long long)drow * ldc + col)
                        = make_float2(v0, v1);
                } else if (OUT_MODE == 4) {
                    *(float2*)(Cf + (long long)drow * ldc + col) = make_float2(v0, v1);
                } else {
                    if (OUT_MODE == 2) { float rb2 = bias[row]; v0 += rb2; v1 += rb2; }
                    else               { v0 += bias[col]; v1 += bias[col + 1]; }
                    __nv_bfloat16 h0 = __float2bfloat16_rn(v0);
                    __nv_bfloat16 h1 = __float2bfloat16_rn(v1);
                    __nv_bfloat16 l0 = __float2bfloat16_rn(v0 - __bfloat162float(h0));
                    __nv_bfloat16 l1 = __float2bfloat16_rn(v1 - __bfloat162float(h1));
                    __nv_bfloat162 hp; hp.x = h0; hp.y = h1;
                    __nv_bfloat162 lp; lp.x = l0; lp.y = l1;
                    *(__nv_bfloat162*)(Ch + bz * strideC + (long long)drow * ldc + col) = hp;
                    *(__nv_bfloat162*)(Cl + bz * strideC + (long long)drow * ldc + col) = lp;
                }
            }
        }
    }
}

// --------------------------- compaction ------------------------------------
__global__ __launch_bounds__(256)
void compact_kernel(const int* __restrict__ mask, int* __restrict__ cnt,
                    int* __restrict__ c2o, int* __restrict__ o2s)
{
    const int b = blockIdx.x, tid = threadIdx.x;
    const int lane = tid & 31, wid = tid >> 5;
    const int* m = mask + b * S_;
    __shared__ int wsum[8];
    __shared__ int s_tot;

    int loc[8], c = 0;
    #pragma unroll
    for (int i = 0; i < 8; i++) { loc[i] = (m[tid * 8 + i] != 0); c += loc[i]; }
    int pre = c;
    #pragma unroll
    for (int o = 1; o < 32; o <<= 1) {
        int v = __shfl_up_sync(0xffffffffu, pre, o);
        if (lane >= o) pre += v;
    }
    if (lane == 31) wsum[wid] = pre;
    __syncthreads();
    int wbase = 0;
    for (int w = 0; w < wid; w++) wbase += wsum[w];
    int slot = wbase + pre - c;
    #pragma unroll
    for (int i = 0; i < 8; i++) {
        int s = tid * 8 + i;
        if (loc[i]) { c2o[b * S_ + slot] = b * S_ + s; o2s[b * S_ + s] = slot; slot++; }
        else        { o2s[b * S_ + s] = -1; }
    }
    if (tid == 0) {
        int tot = 0;
        for (int w = 0; w < 8; w++) tot += wsum[w];
        cnt[b] = tot;
        s_tot = tot;
    }
    __syncthreads();
    for (int s = s_tot + tid; s < S_; s += 256) c2o[b * S_ + s] = -1;
}

// ------------------------- elementwise kernels -----------------------------
__global__ __launch_bounds__(256)
void split_kernel(const float* __restrict__ x, __nv_bfloat16* __restrict__ h,
                  __nv_bfloat16* __restrict__ l, int n)
{
    int i = (blockIdx.x * 256 + threadIdx.x) * 4;
    if (i + 3 < n) {
        float4 v = *(const float4*)(x + i);
        float vv[4] = {v.x, v.y, v.z, v.w};
        #pragma unroll
        for (int q = 0; q < 4; q++) {
            __nv_bfloat16 hh = __float2bfloat16_rn(vv[q]);
            h[i + q] = hh;
            l[i + q] = __float2bfloat16_rn(vv[q] - __bfloat162float(hh));
        }
    }
}

__global__ __launch_bounds__(256)
void transpose_split3_kernel(const float* __restrict__ Wq, const float* __restrict__ Wk,
                             const float* __restrict__ Wv,
                             __nv_bfloat16* __restrict__ qh, __nv_bfloat16* __restrict__ ql,
                             __nv_bfloat16* __restrict__ kh, __nv_bfloat16* __restrict__ kl,
                             __nv_bfloat16* __restrict__ vh, __nv_bfloat16* __restrict__ vl)
{
    int idx = blockIdx.x * 256 + threadIdx.x;
    if (idx >= D_ * D_) return;
    int j = idx / D_, i = idx - j * D_;
    const float* W = (blockIdx.y == 0) ? Wq : (blockIdx.y == 1) ? Wk : Wv;
    __nv_bfloat16* th = (blockIdx.y == 0) ? qh : (blockIdx.y == 1) ? kh : vh;
    __nv_bfloat16* tl = (blockIdx.y == 0) ? ql : (blockIdx.y == 1) ? kl : vl;
    float v = W[i * D_ + j];
    __nv_bfloat16 hh = __float2bfloat16_rn(v);
    th[idx] = hh;
    tl[idx] = __float2bfloat16_rn(v - __bfloat162float(hh));
}

__global__ __launch_bounds__(256)
void vmean_kernel(const __nv_bfloat16* __restrict__ vth,
                  const __nv_bfloat16* __restrict__ vtl, float* __restrict__ mv)
{
    const int d = blockIdx.x, b = blockIdx.y, tid = threadIdx.x;
    const __nv_bfloat16* ph = vth + (long long)d * MTOT + b * S_;
    const __nv_bfloat16* pl = vtl + (long long)d * MTOT + b * S_;
    float s = 0.f;
    #pragma unroll
    for (int i = 0; i < 8; i++) {
        int t = tid + i * 256;
        s += __bfloat162float(ph[t]) + __bfloat162float(pl[t]);
    }
    #pragma unroll
    for (int o = 16; o; o >>= 1) s += __shfl_xor_sync(0xffffffffu, s, o);
    __shared__ float ws[8];
    if ((tid & 31) == 0) ws[tid >> 5] = s;
    __syncthreads();
    if (tid == 0) {
        float t = 0.f;
        for (int w = 0; w < 8; w++) t += ws[w];
        mv[b * D_ + d] = t * (NORM_CONST / (float)S_);
    }
}

__global__ __launch_bounds__(256)
void fill_masked_kernel(const int* __restrict__ mask, const float* __restrict__ mv,
                        float* __restrict__ out)
{
    const int row = blockIdx.x;
    if (mask[row] != 0) return;
    const int b = row >> 11, tid = threadIdx.x;
    #pragma unroll
    for (int i = 0; i < 3; i++) {
        int d = tid + i * 256;
        out[(long long)row * D_ + d] = mv[b * D_ + d];
    }
}

// ------------------------------ softmax ------------------------------------
__global__ __launch_bounds__(256)
void softmax_kernel(const int* __restrict__ cnt, const float* __restrict__ S,
                    __nv_bfloat16* __restrict__ Ah, __nv_bfloat16* __restrict__ Al)
{
    const long long row = blockIdx.x;
    const int b = (int)(row >> 11), r = (int)(row & (S_ - 1));
    const int c = cnt[b];
    const int cpad = (c + 127) & ~127;
    if (r >= cpad) return;
    const int tid = threadIdx.x;
    __nv_bfloat16* ph = Ah + row * S_;
    __nv_bfloat16* pl = Al + row * S_;
    if (r >= c) {
        __nv_bfloat162 z; z.x = __float2bfloat16_rn(0.f); z.y = z.x;
        #pragma unroll
        for (int i = 0; i < 4; i++) {
            ((__nv_bfloat162*)ph)[tid + i * 256] = z;
            ((__nv_bfloat162*)pl)[tid + i * 256] = z;
        }
        return;
    }
    const float* p = S + row * S_;
    __shared__ float sred[8];

    float v[8];
    float mx = -3.0e38f;
    #pragma unroll
    for (int i = 0; i < 8; i++) { v[i] = p[tid + i * 256]; mx = fmaxf(mx, v[i]); }
    #pragma unroll
    for (int o = 16; o; o >>= 1) mx = fmaxf(mx, __shfl_xor_sync(0xffffffffu, mx, o));
    if ((tid & 31) == 0) sred[tid >> 5] = mx;
    __syncthreads();
    float rowmax = sred[0];
    #pragma unroll
    for (int w = 1; w < 8; w++) rowmax = fmaxf(rowmax, sred[w]);
    __syncthreads();

    float s = 0.f;
    #pragma unroll
    for (int i = 0; i < 8; i++) { v[i] = __expf(v[i] - rowmax); s += v[i]; }
    #pragma unroll
    for (int o = 16; o; o >>= 1) s += __shfl_xor_sync(0xffffffffu, s, o);
    if ((tid & 31) == 0) sred[tid >> 5] = s;
    __syncthreads();
    float rowsum = 0.f;
    #pragma unroll
    for (int w = 0; w < 8; w++) rowsum += sred[w];

    const float scale = NORM_CONST / rowsum;
    #pragma unroll
    for (int i = 0; i < 8; i++) {
        float a = v[i] * scale;
        __nv_bfloat16 hh = __float2bfloat16_rn(a);
        ph[tid + i * 256] = hh;
        pl[tid + i * 256] = __float2bfloat16_rn(a - __bfloat162float(hh));
    }
}

// ------------------------------- launch ------------------------------------
extern "C" void kernel_launch(void* const* d_in, const int* in_sizes, int n_in,
                              void* d_out, int out_size)
{
    const float* x    = (const float*)d_in[0];
    const int*   mask = (const int*)  d_in[1];
    const float* Wq   = (const float*)d_in[2];
    const float* bq   = (const float*)d_in[3];
    const float* Wk   = (const float*)d_in[4];
    const float* bk   = (const float*)d_in[5];
    const float* Wv   = (const float*)d_in[6];
    const float* bv   = (const float*)d_in[7];
    float* out = (float*)d_out;

    __nv_bfloat16 *xh, *xl, *WqTh, *WqTl, *WkTh, *WkTl, *WvTh, *WvTl;
    __nv_bfloat16 *Qh, *Ql, *Kh, *Kl, *VTh, *VTl, *Atth, *Attl;
    float *Sc, *mv;
    int *cnt, *c2o, *o2s;
    cudaGetSymbolAddress((void**)&xh, g_xh);     cudaGetSymbolAddress((void**)&xl, g_xl);
    cudaGetSymbolAddress((void**)&WqTh, g_WqTh); cudaGetSymbolAddress((void**)&WqTl, g_WqTl);
    cudaGetSymbolAddress((void**)&WkTh, g_WkTh); cudaGetSymbolAddress((void**)&WkTl, g_WkTl);
    cudaGetSymbolAddress((void**)&WvTh, g_WvTh); cudaGetSymbolAddress((void**)&WvTl, g_WvTl);
    cudaGetSymbolAddress((void**)&Qh, g_Qh);     cudaGetSymbolAddress((void**)&Ql, g_Ql);
    cudaGetSymbolAddress((void**)&Kh, g_Kh);     cudaGetSymbolAddress((void**)&Kl, g_Kl);
    cudaGetSymbolAddress((void**)&VTh, g_VTh);   cudaGetSymbolAddress((void**)&VTl, g_VTl);
    cudaGetSymbolAddress((void**)&Sc, g_S);
    cudaGetSymbolAddress((void**)&Atth, g_Ah);   cudaGetSymbolAddress((void**)&Attl, g_Al);
    cudaGetSymbolAddress((void**)&cnt, g_cnt);
    cudaGetSymbolAddress((void**)&c2o, g_c2o);   cudaGetSymbolAddress((void**)&o2s, g_o2s);
    cudaGetSymbolAddress((void**)&mv, g_mv);

    cudaFuncSetAttribute(mma_gemm_kernel<0>, cudaFuncAttributeMaxDynamicSharedMemorySize, GEMM_SMEM);
    cudaFuncSetAttribute(mma_gemm_kernel<1>, cudaFuncAttributeMaxDynamicSharedMemorySize, GEMM_SMEM);
    cudaFuncSetAttribute(mma_gemm_kernel<2>, cudaFuncAttributeMaxDynamicSharedMemorySize, GEMM_SMEM);
    cudaFuncSetAttribute(mma_gemm_kernel<3>, cudaFuncAttributeMaxDynamicSharedMemorySize, GEMM_SMEM);
    cudaFuncSetAttribute(mma_gemm_kernel<4>, cudaFuncAttributeMaxDynamicSharedMemorySize, GEMM_SMEM);

    dim3 blk(256);

    // 1) compaction
    compact_kernel<<<B_, blk>>>(mask, cnt, c2o, o2s);
    // 2) x split
    split_kernel<<<(MTOT * D_ / 4 + 255) / 256, blk>>>(x, xh, xl, MTOT * D_);
    // 3) weight transpose+split
    {
        dim3 g((D_ * D_ + 255) / 256, 3);
        transpose_split3_kernel<<<g, blk>>>(Wq, Wk, Wv, WqTh, WqTl, WkTh, WkTl, WvTh, WvTl);
    }
    // 4) Q proj on compacted rows only (gather via c2o, early-exit past cnt)
    {
        dim3 grid(D_ / 128, S_ / 128, B_);
        mma_gemm_kernel<3><<<grid, blk, GEMM_SMEM>>>(
            xh, xl, D_, 0, WqTh, WqTl, D_, 0,
            nullptr, Qh, Ql, D_, (long long)S_ * D_, bq, D_, cnt, c2o);
    }
    // 5) K proj (full)
    {
        dim3 grid(D_ / 128, MTOT / 128, 1);
        mma_gemm_kernel<1><<<grid, blk, GEMM_SMEM>>>(
            xh, xl, D_, 0, WkTh, WkTl, D_, 0,
            nullptr, Kh, Kl, D_, 0, bk, D_, nullptr, nullptr);
    }
    // 6) V^T proj (profiled launch under ncu -s 5 -c 1)
    {
        dim3 grid(MTOT / 128, D_ / 128, 1);
        mma_gemm_kernel<2><<<grid, blk, GEMM_SMEM>>>(
            WvTh, WvTl, D_, 0, xh, xl, D_, 0,
            nullptr, VTh, VTl, MTOT, 0, bv, D_, nullptr, nullptr);
    }
    // 7) scores = Qc @ K^T (early exit beyond cnt)
    {
        dim3 grid(S_ / 128, S_ / 128, B_);
        mma_gemm_kernel<0><<<grid, blk, GEMM_SMEM>>>(
            Qh, Ql, D_, (long long)S_ * D_,
            Kh, Kl, D_, (long long)S_ * D_,
            Sc, nullptr, nullptr, S_, (long long)S_ * S_, nullptr, D_, cnt, nullptr);
    }
    // 8) per-batch V mean
    {
        dim3 g(D_, B_);
        vmean_kernel<<<g, blk>>>(VTh, VTl, mv);
    }
    // 9) softmax on compacted rows (+pad zero-fill)
    softmax_kernel<<<MTOT, blk>>>(cnt, Sc, Atth, Attl);
    // 10) out(unmasked) = attn @ V, scatter rows via c2o
    {
        dim3 grid(D_ / 128, S_ / 128, B_);
        mma_gemm_kernel<4><<<grid, blk, GEMM_SMEM>>>(
            Atth, Attl, S_, (long long)S_ * S_,
            VTh, VTl, MTOT, (long long)S_,
            out, nullptr, nullptr, D_, 0, nullptr, S_, cnt, c2o);
    }
    // 11) masked rows = NORM * mean(V[b])
    fill_masked_kernel<<<MTOT, blk>>>(mask, mv, out);
}